// round 13
// baseline (speedup 1.0000x reference)
#include <cuda_runtime.h>

// mean(cumsum(per_sample)) == (1/B) * sum_i per_sample[i] * (B - i)
// Single-pass weighted reduction; WARP-level dynamic chunk stealing to
// remove the per-SM memory-speed spread tail (no block barriers in the
// loop, grab prefetched to hide atomic latency, MLP_p1 kept at 4).
//
// Determinism: g_chunk_sum[chunk] depends only on the chunk (fixed
// intra-chunk order); finalize walks chunks in fixed index order.
// Graph-replay safety: grabs/launch = NWARPS + nchunks exactly; done
// counter = GRID; both atomicInc wraps return counters to 0.

#define WBCE_EPS 1e-10f
#define GRID_MAIN 888          // 148 SMs * 6 resident blocks
#define THREADS_MAIN 256
#define NWARPS (GRID_MAIN * (THREADS_MAIN / 32))   // 7104
#define CHUNK_Q 512            // float4 groups per chunk (16 KB traffic)
#define MAX_CHUNKS 32768       // N4 = 2^24 -> exactly 32768 chunks

__device__ double g_chunk_sum[MAX_CHUNKS];
__device__ unsigned int g_chunk = 0;   // work counter, self-wrapping
__device__ unsigned int g_done = 0;    // done counter, self-wrapping

__device__ __forceinline__ float elem_term(float l, float t, float wP, float wN) {
    // t is exactly 0.0f or 1.0f; dead branch contributes exactly 0
    bool pos = (t != 0.0f);
    float x = pos ? l : (1.0f - l);
    float w = pos ? wP : wN;
    return w * __logf(x + WBCE_EPS);
}

__device__ __forceinline__ int grab_chunk(int lane, unsigned int wrap) {
    unsigned int c = 0;
    if (lane == 0) c = atomicInc(&g_chunk, wrap);
    return (int)__shfl_sync(0xffffffffu, c, 0);
}

__global__ __launch_bounds__(THREADS_MAIN, 6) void wbce_fused_kernel(
    const float* __restrict__ logits,
    const float* __restrict__ targets,
    const float* __restrict__ wp,
    const float* __restrict__ wn,
    float* __restrict__ out,
    int N4,                 // float4 groups = B*2
    int nchunks,            // ceil(N4 / CHUNK_Q)
    unsigned int grab_wrap) // NWARPS + nchunks - 1
{
    __shared__ float swp[8];
    __shared__ float swn[8];
    if (threadIdx.x < 8) {
        swp[threadIdx.x] = wp[threadIdx.x];
        swn[threadIdx.x] = wn[threadIdx.x];
    }
    __syncthreads();

    const int lane = threadIdx.x & 31;
    // idx = base + k*32 + lane, base/k*32 even -> parity(idx) = parity(lane).
    const int cb = (lane & 1) * 4;
    const float w0p = swp[cb + 0], w1p = swp[cb + 1], w2p = swp[cb + 2], w3p = swp[cb + 3];
    const float w0n = swn[cb + 0], w1n = swn[cb + 1], w2n = swn[cb + 2], w3n = swn[cb + 3];

    const float4* __restrict__ lg = (const float4*)logits;
    const float4* __restrict__ tg = (const float4*)targets;
    const int B = N4 >> 1;

    int next = grab_chunk(lane, grab_wrap);
    while (next < nchunks) {
        const int chunk = next;
        next = grab_chunk(lane, grab_wrap);   // prefetch: atomic hides under loads

        const int base = chunk * CHUNK_Q;
        double acc = 0.0;
        // Row weight (B - row): integer <= 2^23, exact in fp32.
        float wrow = (float)(B - (base >> 1) - (lane >> 1));

        if (base + CHUNK_Q <= N4) {
            int idx = base + lane;
            #pragma unroll 1
            for (int j = 0; j < CHUNK_Q / 64; j++) {   // 8 pair-steps
                float4 l0 = __ldg(lg + idx);
                float4 t0 = __ldg(tg + idx);
                float4 l1 = __ldg(lg + idx + 32);
                float4 t1 = __ldg(tg + idx + 32);

                float s0 = elem_term(l0.x, t0.x, w0p, w0n)
                         + elem_term(l0.y, t0.y, w1p, w1n)
                         + elem_term(l0.z, t0.z, w2p, w2n)
                         + elem_term(l0.w, t0.w, w3p, w3n);
                float s1 = elem_term(l1.x, t1.x, w0p, w0n)
                         + elem_term(l1.y, t1.y, w1p, w1n)
                         + elem_term(l1.z, t1.z, w2p, w2n)
                         + elem_term(l1.w, t1.w, w3p, w3n);

                // wrow*s0 + (wrow-16)*s1 ; one double add per pair
                float prod = fmaf(wrow, s0, (wrow - 16.0f) * s1);
                acc -= (double)prod;
                wrow -= 32.0f;
                idx += 64;
            }
        } else {
            // Tail chunk (not hit when N4 % CHUNK_Q == 0)
            for (int idx = base + lane; idx < N4; idx += 32) {
                float4 l0 = __ldg(lg + idx);
                float4 t0 = __ldg(tg + idx);
                float s0 = elem_term(l0.x, t0.x, w0p, w0n)
                         + elem_term(l0.y, t0.y, w1p, w1n)
                         + elem_term(l0.z, t0.z, w2p, w2n)
                         + elem_term(l0.w, t0.w, w3p, w3n);
                float w = (float)(B - (idx >> 1));
                acc -= (double)(w * s0);
            }
        }

        // warp reduce this chunk (fixed order -> deterministic per chunk id)
        #pragma unroll
        for (int off = 16; off > 0; off >>= 1)
            acc += __shfl_down_sync(0xffffffffu, acc, off);
        if (lane == 0) g_chunk_sum[chunk] = acc;
    }

    __threadfence();   // publish this thread's chunk-sum stores device-wide
    __syncthreads();

    // ---- last-block finalize ----
    __shared__ bool s_last;
    __shared__ double ssum[THREADS_MAIN / 32];
    if (threadIdx.x == 0) {
        unsigned int old = atomicInc(&g_done, GRID_MAIN - 1);  // wraps to 0
        s_last = (old == GRID_MAIN - 1);
    }
    __syncthreads();

    if (s_last) {
        __threadfence();
        volatile double* vp = g_chunk_sum;
        const int t = threadIdx.x;
        // Fixed deterministic order, 4 independent chains to shorten DADD chain.
        double a0 = 0.0, a1 = 0.0, a2 = 0.0, a3 = 0.0;
        for (int i = t; i < nchunks; i += 4 * THREADS_MAIN) {
            a0 += vp[i];
            if (i + THREADS_MAIN     < nchunks) a1 += vp[i + THREADS_MAIN];
            if (i + 2 * THREADS_MAIN < nchunks) a2 += vp[i + 2 * THREADS_MAIN];
            if (i + 3 * THREADS_MAIN < nchunks) a3 += vp[i + 3 * THREADS_MAIN];
        }
        double a = (a0 + a1) + (a2 + a3);

        #pragma unroll
        for (int off = 16; off > 0; off >>= 1)
            a += __shfl_down_sync(0xffffffffu, a, off);
        if ((t & 31) == 0) ssum[t >> 5] = a;
        __syncthreads();

        if (t == 0) {
            double tot = 0.0;
            #pragma unroll
            for (int w = 0; w < THREADS_MAIN / 32; w++) tot += ssum[w];
            out[0] = (float)(tot / (double)B);
        }
    }
}

extern "C" void kernel_launch(void* const* d_in, const int* in_sizes, int n_in,
                              void* d_out, int out_size) {
    const float* logits  = (const float*)d_in[0];
    const float* targets = (const float*)d_in[1];
    const float* wp      = (const float*)d_in[2];
    const float* wn      = (const float*)d_in[3];

    const int n_elem = in_sizes[0];           // B * 8 = 2^26, fits int32
    const int N4 = n_elem >> 2;               // float4 groups
    int nchunks = (N4 + CHUNK_Q - 1) / CHUNK_Q;
    if (nchunks > MAX_CHUNKS) nchunks = MAX_CHUNKS;  // not hit for this shape
    const unsigned int grab_wrap = (unsigned int)(NWARPS + nchunks) - 1u;

    wbce_fused_kernel<<<GRID_MAIN, THREADS_MAIN>>>(logits, targets, wp, wn,
                                                   (float*)d_out, N4, nchunks,
                                                   grab_wrap);
}

// round 14
// speedup vs baseline: 1.4477x; 1.4477x over previous
#include <cuda_runtime.h>

// mean(cumsum(per_sample)) == (1/B) * sum_i per_sample[i] * (B - i)
// Single-pass weighted reduction; single kernel, last-block finalize.
// GRID = 888 = 148 SMs * 6 blocks (<=40 regs via launch_bounds, 256 thr)
// -> exactly ONE wave at 48 warps/SM. Plain __ldg LDG.128 loads.
//
// FINAL: measured 81.95/81.95/82.14us (DRAM 81%, 6.65 TB/s). All
// structural deviations regressed: __ldcs +4us, block chunk-steal +14us,
// v8.f32 loads +24us, warp chunk-steal +36us (single-address atomic
// serialization). This is the practical HBM ceiling for the 537 MB
// read-once stream.

#define WBCE_EPS 1e-10f
#define GRID_MAIN 888
#define THREADS_MAIN 256

__device__ double g_partials[GRID_MAIN];
__device__ unsigned int g_done = 0;   // self-resets via atomicInc wraparound

__device__ __forceinline__ float elem_term(float l, float t, float wP, float wN) {
    // t is exactly 0.0f or 1.0f; dead branch contributes exactly 0
    bool pos = (t != 0.0f);
    float x = pos ? l : (1.0f - l);
    float w = pos ? wP : wN;
    return w * __logf(x + WBCE_EPS);
}

__global__ __launch_bounds__(THREADS_MAIN, 6) void wbce_fused_kernel(
    const float* __restrict__ logits,
    const float* __restrict__ targets,
    const float* __restrict__ wp,
    const float* __restrict__ wn,
    float* __restrict__ out,
    int N4)   // float4 groups = B*2 (C=8 -> 2 groups per row), fits int32
{
    __shared__ float swp[8];
    __shared__ float swn[8];
    if (threadIdx.x < 8) {
        swp[threadIdx.x] = wp[threadIdx.x];
        swn[threadIdx.x] = wn[threadIdx.x];
    }
    __syncthreads();

    const int stride = GRID_MAIN * THREADS_MAIN;            // even
    const int tid = blockIdx.x * THREADS_MAIN + threadIdx.x;

    // Channel half (0..3 or 4..7) fixed per thread (stride even).
    const int cb = (tid & 1) * 4;
    const float w0p = swp[cb + 0], w1p = swp[cb + 1], w2p = swp[cb + 2], w3p = swp[cb + 3];
    const float w0n = swn[cb + 0], w1n = swn[cb + 1], w2n = swn[cb + 2], w3n = swn[cb + 3];

    const float4* __restrict__ lg = (const float4*)logits;
    const float4* __restrict__ tg = (const float4*)targets;

    const int B = N4 >> 1;
    // Row weight (B - i): integer <= 2^23, exact in fp32 throughout.
    float wrow = (float)(B - (tid >> 1));
    const float wstep = (float)(stride >> 1);

    double acc = 0.0;
    int idx = tid;

    // Unroll x2: 4 independent LDG.128 in flight per thread.
    for (; idx + stride < N4; idx += 2 * stride) {
        float4 l0 = __ldg(lg + idx);
        float4 t0 = __ldg(tg + idx);
        float4 l1 = __ldg(lg + idx + stride);
        float4 t1 = __ldg(tg + idx + stride);

        float s0 = elem_term(l0.x, t0.x, w0p, w0n)
                 + elem_term(l0.y, t0.y, w1p, w1n)
                 + elem_term(l0.z, t0.z, w2p, w2n)
                 + elem_term(l0.w, t0.w, w3p, w3n);
        float s1 = elem_term(l1.x, t1.x, w0p, w0n)
                 + elem_term(l1.y, t1.y, w1p, w1n)
                 + elem_term(l1.z, t1.z, w2p, w2n)
                 + elem_term(l1.w, t1.w, w3p, w3n);

        // wrow*s0 + (wrow - wstep)*s1, all fp32; one double add per pair.
        float prod = fmaf(wrow, s0, (wrow - wstep) * s1);
        acc -= (double)prod;
        wrow -= 2.0f * wstep;
    }
    if (idx < N4) {
        float4 l0 = __ldg(lg + idx);
        float4 t0 = __ldg(tg + idx);
        float s0 = elem_term(l0.x, t0.x, w0p, w0n)
                 + elem_term(l0.y, t0.y, w1p, w1n)
                 + elem_term(l0.z, t0.z, w2p, w2n)
                 + elem_term(l0.w, t0.w, w3p, w3n);
        acc -= (double)(wrow * s0);
    }

    // ---- block reduce (double) ----
    #pragma unroll
    for (int off = 16; off > 0; off >>= 1)
        acc += __shfl_down_sync(0xffffffffu, acc, off);

    __shared__ double ssum[THREADS_MAIN / 32];
    const int warp = threadIdx.x >> 5;
    if ((threadIdx.x & 31) == 0) ssum[warp] = acc;
    __syncthreads();

    // ---- last-block finalize ----
    __shared__ bool s_last;
    if (threadIdx.x == 0) {
        double b = 0.0;
        #pragma unroll
        for (int w = 0; w < THREADS_MAIN / 32; w++) b += ssum[w];
        g_partials[blockIdx.x] = b;
        __threadfence();
        unsigned int old = atomicInc(&g_done, GRID_MAIN - 1);  // wraps to 0
        s_last = (old == GRID_MAIN - 1);
    }
    __syncthreads();

    if (s_last) {
        __threadfence();
        volatile double* vp = g_partials;
        double a = 0.0;
        for (int i = threadIdx.x; i < GRID_MAIN; i += THREADS_MAIN)
            a += vp[i];

        #pragma unroll
        for (int off = 16; off > 0; off >>= 1)
            a += __shfl_down_sync(0xffffffffu, a, off);

        if ((threadIdx.x & 31) == 0) ssum[warp] = a;
        __syncthreads();

        if (threadIdx.x == 0) {
            double tot = 0.0;
            #pragma unroll
            for (int w = 0; w < THREADS_MAIN / 32; w++) tot += ssum[w];
            out[0] = (float)(tot / (double)B);
        }
    }
}

extern "C" void kernel_launch(void* const* d_in, const int* in_sizes, int n_in,
                              void* d_out, int out_size) {
    const float* logits  = (const float*)d_in[0];
    const float* targets = (const float*)d_in[1];
    const float* wp      = (const float*)d_in[2];
    const float* wn      = (const float*)d_in[3];

    const int n_elem = in_sizes[0];   // B * 8 = 2^26, fits int32
    const int N4 = n_elem >> 2;       // float4 groups

    wbce_fused_kernel<<<GRID_MAIN, THREADS_MAIN>>>(logits, targets, wp, wn,
                                                   (float*)d_out, N4);
}